// round 6
// baseline (speedup 1.0000x reference)
#include <cuda_runtime.h>
#include <cuda_bf16.h>

// out[k][d] = mult_k * sum_i W_k[eb_input[i]][d]   (offsets mathematically dead:
// every index position lands in some bag and all bags are summed).
//
// hist : 1 u32 global RED per index (REDG/L2-atomic bound, ~floor).
// sweep: block-chunked weighted reduction, fully coalesced table loads, counts
//        staged in smem. Tables stay L2-resident across graph replays -> default
//        (fill) cache policy on table loads. Finalize fused via last-block ticket.

#define MAX_EMB 2000000
#define CHUNK_ROWS 1024          // rows per sweep block
#define CHUNK_F4   768           // 1024 rows * 3 floats / 4

// 8MB u32 counts. Zeroed at load; sweep re-zeroes after reading -> clean state
// for every graph replay.
__device__ unsigned int g_count[MAX_EMB];
// 9 double accumulators padded to 512B stride (distinct L2 slices).
__device__ double g_acc[9 * 64];
__device__ unsigned int g_done;  // last-block ticket, reset each replay

// ---------------------------------------------------------------------------
// Kernel 1: histogram. One int4 (4 indices) per thread, 4 REDs.
// ---------------------------------------------------------------------------
__global__ void k_hist(const int* __restrict__ idx, int n_idx) {
    int t = blockIdx.x * blockDim.x + threadIdx.x;
    int n4 = n_idx >> 2;
    if (t < n4) {
        int4 a = __ldcs((const int4*)idx + t);   // index stream: evict-first
        atomicAdd(&g_count[a.x], 1u);
        atomicAdd(&g_count[a.y], 1u);
        atomicAdd(&g_count[a.z], 1u);
        atomicAdd(&g_count[a.w], 1u);
    }
    if (blockIdx.x == 0) {                       // scalar tail
        int rem = n_idx & 3;
        if ((int)threadIdx.x < rem)
            atomicAdd(&g_count[idx[(n4 << 2) + threadIdx.x]], 1u);
    }
}

// ---------------------------------------------------------------------------
// Kernel 2: coalesced weighted sweep + fused finalize.
// Block b owns rows [b*1024, b*1024+1024). Counts staged in smem; table loads
// coalesced (thread tid reads float4 index j*256+tid of the block's 768-f4 chunk).
// ---------------------------------------------------------------------------
__global__ void __launch_bounds__(256) k_sweep(
        const float* __restrict__ W0,
        const float* __restrict__ W1,
        const float* __restrict__ W2,
        int num_emb, float* __restrict__ out,
        unsigned int nblocks) {
    __shared__ float cnt_s[CHUNK_ROWS];
    __shared__ float s_red[8][9];
    __shared__ bool  s_last;

    int tid = threadIdx.x;
    int b = blockIdx.x;
    int row_base = b * CHUNK_ROWS;
    int rows = num_emb - row_base;
    if (rows > CHUNK_ROWS) rows = CHUNK_ROWS;

    // ---- stage counts (coalesced uint4), convert to float, re-zero ----
    int r = tid * 4;
    if (r + 4 <= rows) {
        uint4 c = *(const uint4*)&g_count[row_base + r];
        *(uint4*)&g_count[row_base + r] = make_uint4(0u, 0u, 0u, 0u);
        cnt_s[r + 0] = (float)c.x;
        cnt_s[r + 1] = (float)c.y;
        cnt_s[r + 2] = (float)c.z;
        cnt_s[r + 3] = (float)c.w;
    } else {
#pragma unroll
        for (int m = 0; m < 4; m++) {
            if (r + m < rows) {
                cnt_s[r + m] = (float)g_count[row_base + r + m];
                g_count[row_base + r + m] = 0u;
            }
        }
    }
    __syncthreads();

    // ---- coalesced table sweep ----
    float acc[9];
#pragma unroll
    for (int k = 0; k < 9; k++) acc[k] = 0.0f;

    int nf_local = rows * 3;                      // valid floats in this chunk
    long long nf_total = (long long)num_emb * 3;  // floats per table
    const float* Ws[3] = {W0, W1, W2};

#pragma unroll
    for (int k = 0; k < 3; k++) {
        const float4* base = (const float4*)Ws[k] + (long long)b * CHUNK_F4;
#pragma unroll
        for (int j = 0; j < 3; j++) {
            int q = j * 256 + tid;                // f4 index within chunk
            int local0 = q * 4;
            if (local0 < nf_local) {
                long long gf = (long long)b * (CHUNK_F4 * 4) + local0;
                float f[4];
                if (gf + 4 <= nf_total) {
                    float4 v = __ldg(base + q);
                    f[0] = v.x; f[1] = v.y; f[2] = v.z; f[3] = v.w;
                } else {                           // rare ragged table end
                    const float* fb = (const float*)base;
#pragma unroll
                    for (int m = 0; m < 4; m++)
                        f[m] = (gf + m < nf_total) ? fb[local0 + m] : 0.0f;
                }
#pragma unroll
                for (int m = 0; m < 4; m++) {
                    int local = local0 + m;
                    if (local < nf_local) {
                        int row = local / 3;       // constant-div (mul/shift)
                        int dim = local - row * 3;
                        acc[3 * k + dim] += cnt_s[row] * f[m];
                    }
                }
            }
        }
    }

    // ---- block reduction ----
    unsigned lane = tid & 31u;
    unsigned warp = tid >> 5;
#pragma unroll
    for (int k = 0; k < 9; k++) {
#pragma unroll
        for (int o = 16; o > 0; o >>= 1)
            acc[k] += __shfl_down_sync(0xffffffffu, acc[k], o);
    }
    if (lane == 0) {
#pragma unroll
        for (int k = 0; k < 9; k++) s_red[warp][k] = acc[k];
    }
    __syncthreads();

    if (tid < 9) {
        double s = 0.0;
#pragma unroll
        for (int w = 0; w < 8; w++) s += (double)s_red[w][tid];
        atomicAdd(&g_acc[tid * 64], s);
    }
    __threadfence();
    __syncthreads();

    if (tid == 0)
        s_last = (atomicAdd(&g_done, 1u) == nblocks - 1);
    __syncthreads();

    if (s_last) {
        if (tid < 9) {
            const float mult[3] = {5.0f, 10.0f, 6.0f};
            double v = g_acc[tid * 64];
            g_acc[tid * 64] = 0.0;                 // reset for next replay
            out[tid] = (float)((double)mult[tid / 3] * v);
        }
        if (tid == 0) g_done = 0u;                 // reset ticket
    }
}

// ---------------------------------------------------------------------------
extern "C" void kernel_launch(void* const* d_in, const int* in_sizes, int n_in,
                              void* d_out, int out_size) {
    const int*   idx = (const int*)d_in[0];
    // d_in[1] = eb_offset : mathematically unused
    const float* W0  = (const float*)d_in[2];
    const float* W1  = (const float*)d_in[3];
    const float* W2  = (const float*)d_in[4];
    int n_idx   = in_sizes[0];
    int num_emb = in_sizes[2] / 3;

    int n4 = n_idx >> 2;
    int hist_blocks = (n4 + 255) / 256;
    if (hist_blocks < 1) hist_blocks = 1;
    k_hist<<<hist_blocks, 256>>>(idx, n_idx);

    int sweep_blocks = (num_emb + CHUNK_ROWS - 1) / CHUNK_ROWS;
    if (sweep_blocks < 1) sweep_blocks = 1;
    k_sweep<<<sweep_blocks, 256>>>(W0, W1, W2, num_emb, (float*)d_out,
                                   (unsigned int)sweep_blocks);
}

// round 7
// speedup vs baseline: 2.1097x; 2.1097x over previous
#include <cuda_runtime.h>
#include <cuda_bf16.h>

// out[k][d] = mult_k * sum_i W_k[eb_input[i]][d]   (offsets mathematically dead:
// every index position lands in some bag and all bags are summed).
//
// hist : 1 u32 global RED per index (REDG/L2-atomic floor ~19.5us).
// sweep: EXACT R1 form (measured 10.4us): 4 rows/thread, uint4 count read+zero,
//        3x float4 __ldg per table (tables L2-resident across graph replays).
//        Finalize fused into the last sweep block via a global ticket.

#define MAX_EMB 2000000

// 8MB u32 counts. Zeroed at load; sweep re-zeroes after reading -> clean state
// for every graph replay.
__device__ unsigned int g_count[MAX_EMB];
// 9 double accumulators padded to 512B stride (distinct L2 slices).
__device__ double g_acc[9 * 64];
__device__ unsigned int g_done;   // last-block ticket, reset each replay

// ---------------------------------------------------------------------------
// Kernel 1: histogram. One int4 (4 indices) per thread, 4 REDs.
// ---------------------------------------------------------------------------
__global__ void k_hist(const int* __restrict__ idx, int n_idx) {
    int t = blockIdx.x * blockDim.x + threadIdx.x;
    int n4 = n_idx >> 2;
    if (t < n4) {
        int4 a = __ldcs((const int4*)idx + t);   // index stream: evict-first
        atomicAdd(&g_count[a.x], 1u);
        atomicAdd(&g_count[a.y], 1u);
        atomicAdd(&g_count[a.z], 1u);
        atomicAdd(&g_count[a.w], 1u);
    }
    if (blockIdx.x == 0) {                       // scalar tail
        int rem = n_idx & 3;
        if ((int)threadIdx.x < rem)
            atomicAdd(&g_count[idx[(n4 << 2) + threadIdx.x]], 1u);
    }
}

// ---------------------------------------------------------------------------
// Kernel 2: weighted sweep (R1 form) + fused finalize.
// ---------------------------------------------------------------------------
__global__ void __launch_bounds__(256) k_sweep(
        const float* __restrict__ W0,
        const float* __restrict__ W1,
        const float* __restrict__ W2,
        int num_emb, float* __restrict__ out,
        unsigned int nblocks) {
    int t = blockIdx.x * blockDim.x + threadIdx.x;
    int r0 = t * 4;

    float acc[9];
#pragma unroll
    for (int k = 0; k < 9; k++) acc[k] = 0.0f;

    if (r0 + 4 <= num_emb) {
        uint4 c4 = *(const uint4*)&g_count[r0];
        *(uint4*)&g_count[r0] = make_uint4(0u, 0u, 0u, 0u);   // re-init for replay
        float c0 = (float)c4.x, c1 = (float)c4.y, c2 = (float)c4.z, c3 = (float)c4.w;

        const float* Ws[3] = {W0, W1, W2};
#pragma unroll
        for (int k = 0; k < 3; k++) {
            const float4* Wv = (const float4*)Ws[k] + 3 * t;   // 12 floats = 4 rows
            float4 a = __ldg(Wv + 0);
            float4 b = __ldg(Wv + 1);
            float4 d = __ldg(Wv + 2);
            // rows: r0: a.x a.y a.z | r0+1: a.w b.x b.y | r0+2: b.z b.w d.x | r0+3: d.y d.z d.w
            acc[3 * k + 0] += c0 * a.x + c1 * a.w + c2 * b.z + c3 * d.y;
            acc[3 * k + 1] += c0 * a.y + c1 * b.x + c2 * b.w + c3 * d.z;
            acc[3 * k + 2] += c0 * a.z + c1 * b.y + c2 * d.x + c3 * d.w;
        }
    } else if (r0 < num_emb) {
        for (int r = r0; r < num_emb; r++) {
            float c = (float)g_count[r];
            g_count[r] = 0u;
            const float* Ws[3] = {W0, W1, W2};
#pragma unroll
            for (int k = 0; k < 3; k++) {
                acc[3 * k + 0] += c * Ws[k][3 * r + 0];
                acc[3 * k + 1] += c * Ws[k][3 * r + 1];
                acc[3 * k + 2] += c * Ws[k][3 * r + 2];
            }
        }
    }

    // warp reduction
    unsigned lane = threadIdx.x & 31u;
    unsigned warp = threadIdx.x >> 5;
#pragma unroll
    for (int k = 0; k < 9; k++) {
#pragma unroll
        for (int o = 16; o > 0; o >>= 1)
            acc[k] += __shfl_down_sync(0xffffffffu, acc[k], o);
    }

    __shared__ float s_red[8][9];
    __shared__ bool  s_last;
    if (lane == 0) {
#pragma unroll
        for (int k = 0; k < 9; k++) s_red[warp][k] = acc[k];
    }
    __syncthreads();

    if (threadIdx.x < 9) {
        double s = 0.0;
#pragma unroll
        for (int w = 0; w < 8; w++) s += (double)s_red[w][threadIdx.x];
        atomicAdd(&g_acc[threadIdx.x * 64], s);
    }
    __threadfence();
    __syncthreads();

    if (threadIdx.x == 0)
        s_last = (atomicAdd(&g_done, 1u) == nblocks - 1);
    __syncthreads();

    if (s_last) {
        if (threadIdx.x < 9) {
            const float mult[3] = {5.0f, 10.0f, 6.0f};
            double v = g_acc[threadIdx.x * 64];
            g_acc[threadIdx.x * 64] = 0.0;         // reset for next replay
            out[threadIdx.x] = (float)((double)mult[threadIdx.x / 3] * v);
        }
        if (threadIdx.x == 0) g_done = 0u;         // reset ticket
    }
}

// ---------------------------------------------------------------------------
extern "C" void kernel_launch(void* const* d_in, const int* in_sizes, int n_in,
                              void* d_out, int out_size) {
    const int*   idx = (const int*)d_in[0];
    // d_in[1] = eb_offset : mathematically unused
    const float* W0  = (const float*)d_in[2];
    const float* W1  = (const float*)d_in[3];
    const float* W2  = (const float*)d_in[4];
    int n_idx   = in_sizes[0];
    int num_emb = in_sizes[2] / 3;

    int n4 = n_idx >> 2;
    int hist_blocks = (n4 + 255) / 256;
    if (hist_blocks < 1) hist_blocks = 1;
    k_hist<<<hist_blocks, 256>>>(idx, n_idx);

    int sweep_threads = (num_emb + 3) / 4;
    int sweep_blocks = (sweep_threads + 255) / 256;
    if (sweep_blocks < 1) sweep_blocks = 1;
    k_sweep<<<sweep_blocks, 256>>>(W0, W1, W2, num_emb, (float*)d_out,
                                   (unsigned int)sweep_blocks);
}

// round 8
// speedup vs baseline: 2.1660x; 1.0267x over previous
#include <cuda_runtime.h>
#include <cuda_bf16.h>

// out[k][d] = mult_k * sum_i W_k[eb_input[i]][d]   (offsets mathematically dead:
// every index position lands in some bag and all bags are summed).
//
// hist : 1 u32 global RED per index (L1tex-wavefront + L2-atomic floor ~19.5us).
// sweep: EXACT R1 hot loop (measured 10.4us): 4 rows/thread, uint4 count
//        read+zero, 3x float4 __ldg per table (tables L2-resident across graph
//        replays). Finalize fused into last block; fence by warp 0 only.

#define MAX_EMB 2000000

// 8MB u32 counts. Zeroed at load; sweep re-zeroes after reading -> clean state
// for every graph replay.
__device__ unsigned int g_count[MAX_EMB];
// 9 double accumulators padded to 512B stride (distinct L2 slices).
__device__ double g_acc[9 * 64];
__device__ unsigned int g_done;   // last-block ticket, reset each replay

// ---------------------------------------------------------------------------
// Kernel 1: histogram. One int4 (4 indices) per thread, 4 REDs.
// ---------------------------------------------------------------------------
__global__ void k_hist(const int* __restrict__ idx, int n_idx) {
    int t = blockIdx.x * blockDim.x + threadIdx.x;
    int n4 = n_idx >> 2;
    if (t < n4) {
        int4 a = __ldcs((const int4*)idx + t);   // index stream: evict-first
        atomicAdd(&g_count[a.x], 1u);
        atomicAdd(&g_count[a.y], 1u);
        atomicAdd(&g_count[a.z], 1u);
        atomicAdd(&g_count[a.w], 1u);
    }
    if (blockIdx.x == 0) {                       // scalar tail
        int rem = n_idx & 3;
        if ((int)threadIdx.x < rem)
            atomicAdd(&g_count[idx[(n4 << 2) + threadIdx.x]], 1u);
    }
}

// ---------------------------------------------------------------------------
// Kernel 2: weighted sweep (R1 form) + fused finalize (cheap fence).
// ---------------------------------------------------------------------------
__global__ void k_sweep(const float* __restrict__ W0,
                        const float* __restrict__ W1,
                        const float* __restrict__ W2,
                        int num_emb, float* __restrict__ out,
                        unsigned int nblocks) {
    int t = blockIdx.x * blockDim.x + threadIdx.x;
    int r0 = t * 4;

    float acc[9];
#pragma unroll
    for (int k = 0; k < 9; k++) acc[k] = 0.0f;

    if (r0 + 4 <= num_emb) {
        uint4 c4 = *(const uint4*)&g_count[r0];
        *(uint4*)&g_count[r0] = make_uint4(0u, 0u, 0u, 0u);   // re-init for replay
        float c0 = (float)c4.x, c1 = (float)c4.y, c2 = (float)c4.z, c3 = (float)c4.w;

        const float* Ws[3] = {W0, W1, W2};
#pragma unroll
        for (int k = 0; k < 3; k++) {
            const float4* Wv = (const float4*)Ws[k] + 3 * t;   // 12 floats = 4 rows
            float4 a = __ldg(Wv + 0);
            float4 b = __ldg(Wv + 1);
            float4 d = __ldg(Wv + 2);
            // rows: r0: a.x a.y a.z | r0+1: a.w b.x b.y | r0+2: b.z b.w d.x | r0+3: d.y d.z d.w
            acc[3 * k + 0] += c0 * a.x + c1 * a.w + c2 * b.z + c3 * d.y;
            acc[3 * k + 1] += c0 * a.y + c1 * b.x + c2 * b.w + c3 * d.z;
            acc[3 * k + 2] += c0 * a.z + c1 * b.y + c2 * d.x + c3 * d.w;
        }
    } else if (r0 < num_emb) {
        for (int r = r0; r < num_emb; r++) {
            float c = (float)g_count[r];
            g_count[r] = 0u;
            const float* Ws[3] = {W0, W1, W2};
#pragma unroll
            for (int k = 0; k < 3; k++) {
                acc[3 * k + 0] += c * Ws[k][3 * r + 0];
                acc[3 * k + 1] += c * Ws[k][3 * r + 1];
                acc[3 * k + 2] += c * Ws[k][3 * r + 2];
            }
        }
    }

    // warp reduction
    unsigned lane = threadIdx.x & 31u;
    unsigned warp = threadIdx.x >> 5;
#pragma unroll
    for (int k = 0; k < 9; k++) {
#pragma unroll
        for (int o = 16; o > 0; o >>= 1)
            acc[k] += __shfl_down_sync(0xffffffffu, acc[k], o);
    }

    __shared__ float s_red[8][9];
    __shared__ bool  s_last;
    if (lane == 0) {
#pragma unroll
        for (int k = 0; k < 9; k++) s_red[warp][k] = acc[k];
    }
    __syncthreads();

    // Warp 0 only: global accumulate + fence + ticket (cheap; 32 threads/block).
    if (warp == 0) {
        if (lane < 9) {
            double s = 0.0;
#pragma unroll
            for (int w = 0; w < 8; w++) s += (double)s_red[w][lane];
            atomicAdd(&g_acc[lane * 64], s);
        }
        __threadfence();                 // order g_acc adds before ticket
        __syncwarp();
        bool last = false;
        if (lane == 0)
            last = (atomicAdd(&g_done, 1u) == nblocks - 1);
        last = __shfl_sync(0xffffffffu, last ? 1 : 0, 0) != 0;

        if (last) {
            if (lane < 9) {
                const float mult[3] = {5.0f, 10.0f, 6.0f};
                // volatile: bypass any cached copy, read L2-fresh value
                double v = *(volatile double*)&g_acc[lane * 64];
                *(volatile double*)&g_acc[lane * 64] = 0.0;   // reset for replay
                out[lane] = (float)((double)mult[lane / 3] * v);
            }
            if (lane == 0) g_done = 0u;  // reset ticket for next replay
        }
    }
}

// ---------------------------------------------------------------------------
extern "C" void kernel_launch(void* const* d_in, const int* in_sizes, int n_in,
                              void* d_out, int out_size) {
    const int*   idx = (const int*)d_in[0];
    // d_in[1] = eb_offset : mathematically unused
    const float* W0  = (const float*)d_in[2];
    const float* W1  = (const float*)d_in[3];
    const float* W2  = (const float*)d_in[4];
    int n_idx   = in_sizes[0];
    int num_emb = in_sizes[2] / 3;

    int n4 = n_idx >> 2;
    int hist_blocks = (n4 + 255) / 256;
    if (hist_blocks < 1) hist_blocks = 1;
    k_hist<<<hist_blocks, 256>>>(idx, n_idx);

    int sweep_threads = (num_emb + 3) / 4;
    int sweep_blocks = (sweep_threads + 255) / 256;
    if (sweep_blocks < 1) sweep_blocks = 1;
    k_sweep<<<sweep_blocks, 256>>>(W0, W1, W2, num_emb, (float*)d_out,
                                   (unsigned int)sweep_blocks);
}